// round 2
// baseline (speedup 1.0000x reference)
#include <cuda_runtime.h>
#include <cuda_bf16.h>
#include <mma.h>
#include <cstdint>

using namespace nvcuda;

// ---------------- Problem constants ----------------
#define B_DIM 16
#define T_DIM 8192
#define H_DIM 256
#define N_TOT 512            // rows of [W_lin; W_mem]
#define TILE_M 128           // rows per CTA
#define TILE_N 128           // output cols per CTA (of 256) -> grid.y = 2
#define KC 64                // k-chunk
#define NCHUNKS 4
#define N_TILES 1024         // (B*T)/TILE_M
#define TILES_PER_BATCH 64   // 8192/128
#define TPB 512

// ---------------- SMEM layout ----------------
// chunk buffers (bf16, pitch 72 elems = 144B, conflict-free for ldmatrix)
#define PITCH_K 72
#define OFF_AH 0
#define OFF_AL (OFF_AH + TILE_M * PITCH_K * 2)            // 18432
#define OFF_BH (OFF_AL + TILE_M * PITCH_K * 2)            // 36864
#define OFF_BL (OFF_BH + 256 * PITCH_K * 2)               // 73728
#define SMEM_TOTAL (OFF_BL + 256 * PITCH_K * 2)           // 110592
// epilogue staging (fp32, pitch 68 floats = 272B, mult of 16B), reuses buffers
#define PITCH_E 68
#define OFF_S1 0
#define OFF_S2 (TILE_M * PITCH_E * 4)                     // 34816; S1+S2 = 69632 < SMEM_TOTAL

// ---------------- Device scratch ----------------
__device__ __nv_bfloat16 g_Wh[N_TOT * H_DIM];
__device__ __nv_bfloat16 g_Wl[N_TOT * H_DIM];
__device__ float g_edge[(size_t)N_TILES * 8 * H_DIM];   // last-8-rows of z2 per row-tile

__device__ __forceinline__ void split32(float f, __nv_bfloat16& h, __nv_bfloat16& l){
    h = __float2bfloat16(f);
    l = __float2bfloat16(f - __bfloat162float(h));
}
__device__ __forceinline__ uint32_t pack2(__nv_bfloat16 a, __nv_bfloat16 b){
    __nv_bfloat162 t; t.x = a; t.y = b;
    return *reinterpret_cast<uint32_t*>(&t);
}

// ============ kernel 0: split weights into bf16 hi/lo ============
__global__ void fsmn_convw_kernel(const float* __restrict__ Wlin, const float* __restrict__ Wmem){
    int r = blockIdx.x;           // 0..511
    int k = threadIdx.x;          // 0..255
    float w = (r < 256) ? Wlin[r * H_DIM + k] : Wmem[(r - 256) * H_DIM + k];
    __nv_bfloat16 h, l; split32(w, h, l);
    g_Wh[r * H_DIM + k] = h;
    g_Wl[r * H_DIM + k] = l;
}

// ============ kernel 1: fused dual GEMM + causal window epilogue ============
__global__ void __launch_bounds__(TPB, 1)
fsmn_main_kernel(const float* __restrict__ x,
                 const float* __restrict__ b_lin,
                 const float* __restrict__ b_mem,
                 float* __restrict__ out){
    extern __shared__ char smem[];
    const int tid  = threadIdx.x;
    const int wid  = tid >> 5;
    const int warp_m = wid >> 2;          // 0..3 -> rows warp_m*32
    const int warp_n = wid & 3;           // 0..3 -> cols warp_n*32 (of 128)
    const int row_base = blockIdx.x * TILE_M;
    const int n0 = blockIdx.y * TILE_N;   // output-col base (0 or 128)

    __nv_bfloat16* Ah = reinterpret_cast<__nv_bfloat16*>(smem + OFF_AH);
    __nv_bfloat16* Al = reinterpret_cast<__nv_bfloat16*>(smem + OFF_AL);
    __nv_bfloat16* Bh = reinterpret_cast<__nv_bfloat16*>(smem + OFF_BH);
    __nv_bfloat16* Bl = reinterpret_cast<__nv_bfloat16*>(smem + OFF_BL);

    wmma::fragment<wmma::accumulator, 16, 16, 16, float> acc1[2][2], acc2[2][2];
    #pragma unroll
    for (int m2 = 0; m2 < 2; m2++)
        #pragma unroll
        for (int n2 = 0; n2 < 2; n2++){
            wmma::fill_fragment(acc1[m2][n2], 0.0f);
            wmma::fill_fragment(acc2[m2][n2], 0.0f);
        }

    const int mrow = warp_m * 32;
    const int ncol = warp_n * 32;

    for (int c = 0; c < NCHUNKS; c++){
        __syncthreads();   // previous chunk's compute done before overwrite
        // ---- load + split A chunk: x[row_base..+128)[c*64..+64) -> Ah/Al
        #pragma unroll
        for (int it = 0; it < 8; it++){
            int idx = tid + it * TPB;        // 4096 float2
            int row = idx >> 5;
            int j2  = idx & 31;
            float2 v = *reinterpret_cast<const float2*>(
                x + (size_t)(row_base + row) * H_DIM + c * KC + j2 * 2);
            __nv_bfloat16 h0, l0, h1, l1;
            split32(v.x, h0, l0); split32(v.y, h1, l1);
            uint32_t off = (uint32_t)(row * PITCH_K + j2 * 2);
            *reinterpret_cast<uint32_t*>(&Ah[off]) = pack2(h0, h1);
            *reinterpret_cast<uint32_t*>(&Al[off]) = pack2(l0, l1);
        }
        // ---- load B chunk: rows 0..127 = W_lin[n0..], rows 128..255 = W_mem[n0..]
        #pragma unroll
        for (int it = 0; it < 8; it++){
            int idx = tid + it * TPB;        // 4096 uint2 (4 bf16 each)
            int row = idx >> 4;              // 0..255
            int j   = idx & 15;
            int grow = (row < 128) ? (n0 + row) : (128 + n0 + row);  // 256 + n0 + (row-128)
            uint2 vh = *(reinterpret_cast<const uint2*>(g_Wh + (size_t)grow * H_DIM + c * KC) + j);
            uint2 vl = *(reinterpret_cast<const uint2*>(g_Wl + (size_t)grow * H_DIM + c * KC) + j);
            *reinterpret_cast<uint2*>(&Bh[row * PITCH_K + j * 4]) = vh;
            *reinterpret_cast<uint2*>(&Bl[row * PITCH_K + j * 4]) = vl;
        }
        __syncthreads();

        // ---- compute: 3 split passes (xh*Wh, xh*Wl, xl*Wh), 4 k16 steps
        #pragma unroll
        for (int p = 0; p < 3; p++){
            const __nv_bfloat16* Ab = (p == 2) ? Al : Ah;
            const __nv_bfloat16* Bb = (p == 1) ? Bl : Bh;
            #pragma unroll
            for (int kk = 0; kk < 4; kk++){
                wmma::fragment<wmma::matrix_b, 16, 16, 16, __nv_bfloat16, wmma::col_major> b1[2], b2[2];
                #pragma unroll
                for (int n2 = 0; n2 < 2; n2++){
                    wmma::load_matrix_sync(b1[n2], Bb + (ncol + n2 * 16) * PITCH_K + kk * 16, PITCH_K);
                    wmma::load_matrix_sync(b2[n2], Bb + (128 + ncol + n2 * 16) * PITCH_K + kk * 16, PITCH_K);
                }
                #pragma unroll
                for (int m2 = 0; m2 < 2; m2++){
                    wmma::fragment<wmma::matrix_a, 16, 16, 16, __nv_bfloat16, wmma::row_major> a;
                    wmma::load_matrix_sync(a, Ab + (mrow + m2 * 16) * PITCH_K + kk * 16, PITCH_K);
                    #pragma unroll
                    for (int n2 = 0; n2 < 2; n2++){
                        wmma::mma_sync(acc1[m2][n2], a, b1[n2], acc1[m2][n2]);
                        wmma::mma_sync(acc2[m2][n2], a, b2[n2], acc2[m2][n2]);
                    }
                }
            }
        }
    }

    // ================= epilogue =================
    float* S1 = reinterpret_cast<float*>(smem + OFF_S1);
    float* S2 = reinterpret_cast<float*>(smem + OFF_S2);
    const int first_tile = ((blockIdx.x & (TILES_PER_BATCH - 1)) == 0);
    const int col = tid & 63;
    const int rg  = tid >> 6;         // 0..7 -> rows rg*16..+15

    #pragma unroll
    for (int h = 0; h < 2; h++){
        __syncthreads();
        if ((warp_n >> 1) == h){
            int cbase = (warp_n & 1) * 32;
            #pragma unroll
            for (int m2 = 0; m2 < 2; m2++)
                #pragma unroll
                for (int n2 = 0; n2 < 2; n2++){
                    wmma::store_matrix_sync(S1 + (mrow + m2 * 16) * PITCH_E + cbase + n2 * 16,
                                            acc1[m2][n2], PITCH_E, wmma::mem_row_major);
                    wmma::store_matrix_sync(S2 + (mrow + m2 * 16) * PITCH_E + cbase + n2 * 16,
                                            acc2[m2][n2], PITCH_E, wmma::mem_row_major);
                }
        }
        __syncthreads();

        int gcol = n0 + h * 64 + col;
        float bsum = b_lin[gcol] + b_mem[gcol];
        int r0 = rg * 16;
        float sum8 = 0.f;
        #pragma unroll
        for (int d = 1; d <= 8; d++){
            int rr = r0 - d;
            if (rr >= 0) sum8 += S2[rr * PITCH_E + col];
        }
        #pragma unroll
        for (int i = 0; i < 16; i++){
            int r = r0 + i;
            float cur  = S2[r * PITCH_E + col];
            float wsum = sum8 + cur;                     // rows [max(0,r-8)..r] (in-tile clipped)
            float inv  = (first_tile && r < 8) ? (1.f / (float)(r + 1)) : (1.f / 9.f);
            out[(size_t)(row_base + r) * H_DIM + gcol] = S1[r * PITCH_E + col] + bsum + wsum * inv;
            if (r >= 120)
                g_edge[((size_t)blockIdx.x * 8 + (r - 120)) * H_DIM + gcol] = cur;
            float drop = (r >= 8) ? S2[(r - 8) * PITCH_E + col] : 0.f;
            sum8 += cur - drop;
        }
    }
}

// ============ kernel 2: patch cross-tile window contributions ============
__global__ void fsmn_fix_kernel(float* __restrict__ out){
    int bid = blockIdx.x;                       // 0..1007
    int b  = bid / (TILES_PER_BATCH - 1);
    int jt = bid % (TILES_PER_BATCH - 1) + 1;   // tiles 1..63 within batch
    int prev_tile = b * TILES_PER_BATCH + jt - 1;
    int n = threadIdx.x;                        // column 0..255
    const float* e = &g_edge[(size_t)prev_tile * 8 * H_DIM];
    size_t obase = (size_t)(b * TILES_PER_BATCH + jt) * TILE_M * H_DIM;
    float suf = 0.f;
    #pragma unroll
    for (int jr = 7; jr >= 0; jr--){
        suf += e[jr * H_DIM + n];               // prev rows [120+jr .. 127]
        out[obase + (size_t)jr * H_DIM + n] += suf * (1.f / 9.f);
    }
}

// ============ launch ============
extern "C" void kernel_launch(void* const* d_in, const int* in_sizes, int n_in,
                              void* d_out, int out_size){
    const float* x     = (const float*)d_in[0];
    const float* W_lin = (const float*)d_in[1];
    const float* b_lin = (const float*)d_in[2];
    const float* W_mem = (const float*)d_in[3];
    const float* b_mem = (const float*)d_in[4];
    float* out = (float*)d_out;

    static bool attr_set = false;
    cudaFuncSetAttribute(fsmn_main_kernel, cudaFuncAttributeMaxDynamicSharedMemorySize, SMEM_TOTAL);
    (void)attr_set;

    fsmn_convw_kernel<<<N_TOT, H_DIM>>>(W_lin, W_mem);
    fsmn_main_kernel<<<dim3(N_TILES, 2), TPB, SMEM_TOTAL>>>(x, b_lin, b_mem, out);
    fsmn_fix_kernel<<<B_DIM * (TILES_PER_BATCH - 1), H_DIM>>>(out);
}

// round 3
// speedup vs baseline: 1.0328x; 1.0328x over previous
#include <cuda_runtime.h>
#include <cuda_bf16.h>
#include <mma.h>
#include <cstdint>

using namespace nvcuda;

// ---------------- Problem constants ----------------
#define B_DIM 16
#define T_DIM 8192
#define H_DIM 256
#define N_TOT 512            // rows of [W_lin; W_mem]
#define TILE_M 128           // rows per CTA
#define TILE_N 128           // output cols per CTA -> grid.y = 2
#define KC 64                // k-chunk
#define NCHUNKS 4
#define N_TILES 1024         // (B*T)/TILE_M
#define TILES_PER_BATCH 64
#define TPB 512
#define NROWS_TOTAL (B_DIM * T_DIM)

// ---------------- SMEM layout (double-buffered) ----------------
#define PITCH_K 72                                 // bf16 elems per row (144 B)
#define A_BYTES (TILE_M * PITCH_K * 2)             // 18432 per (h|l)
#define B_BYTES (256 * PITCH_K * 2)                // 36864 per (h|l)
#define OFF_AH 0
#define OFF_AL (OFF_AH + A_BYTES)
#define OFF_BH (OFF_AL + A_BYTES)
#define OFF_BL (OFF_BH + B_BYTES)
#define STAGE_BYTES (OFF_BL + B_BYTES)             // 110592
#define SMEM_TOTAL (2 * STAGE_BYTES)               // 221184
// epilogue staging (fp32, pitch 68) reuses the buffers
#define PITCH_E 68
#define OFF_S1 0
#define OFF_S2 (TILE_M * PITCH_E * 4)              // 34816

// ---------------- Device scratch ----------------
__device__ __nv_bfloat16 g_Wh[N_TOT * H_DIM];
__device__ __nv_bfloat16 g_Wl[N_TOT * H_DIM];
__device__ __nv_bfloat16 g_xh[(size_t)NROWS_TOTAL * H_DIM];
__device__ __nv_bfloat16 g_xl[(size_t)NROWS_TOTAL * H_DIM];
__device__ float g_edge[(size_t)N_TILES * 8 * H_DIM];

__device__ __forceinline__ void split32(float f, __nv_bfloat16& h, __nv_bfloat16& l){
    h = __float2bfloat16(f);
    l = __float2bfloat16(f - __bfloat162float(h));
}
__device__ __forceinline__ uint32_t pack2(__nv_bfloat16 a, __nv_bfloat16 b){
    __nv_bfloat162 t; t.x = a; t.y = b;
    return *reinterpret_cast<uint32_t*>(&t);
}
__device__ __forceinline__ uint32_t smem_u32(const void* p){
    uint32_t a;
    asm("{ .reg .u64 t; cvta.to.shared.u64 t, %1; cvt.u32.u64 %0, t; }" : "=r"(a) : "l"(p));
    return a;
}
__device__ __forceinline__ void cp16(void* dst, const void* src){
    uint32_t d = smem_u32(dst);
    asm volatile("cp.async.cg.shared.global [%0], [%1], 16;" :: "r"(d), "l"(src) : "memory");
}
__device__ __forceinline__ void cp_commit(){ asm volatile("cp.async.commit_group;" ::: "memory"); }
template<int N> __device__ __forceinline__ void cp_wait(){ asm volatile("cp.async.wait_group %0;" :: "n"(N) : "memory"); }

// ============ kernel 0: split weights into bf16 hi/lo ============
__global__ void fsmn_convw_kernel(const float* __restrict__ Wlin, const float* __restrict__ Wmem){
    int r = blockIdx.x, k = threadIdx.x;
    float w = (r < 256) ? Wlin[r * H_DIM + k] : Wmem[(r - 256) * H_DIM + k];
    __nv_bfloat16 h, l; split32(w, h, l);
    g_Wh[r * H_DIM + k] = h;
    g_Wl[r * H_DIM + k] = l;
}

// ============ kernel 0b: split x into bf16 hi/lo ============
__global__ void __launch_bounds__(512) fsmn_convx_kernel(const float* __restrict__ x){
    size_t i = ((size_t)blockIdx.x * 512 + threadIdx.x) * 4;
    float4 v = *reinterpret_cast<const float4*>(x + i);
    __nv_bfloat16 h0,l0,h1,l1,h2,l2,h3,l3;
    split32(v.x,h0,l0); split32(v.y,h1,l1); split32(v.z,h2,l2); split32(v.w,h3,l3);
    uint2 ph = make_uint2(pack2(h0,h1), pack2(h2,h3));
    uint2 pl = make_uint2(pack2(l0,l1), pack2(l2,l3));
    *reinterpret_cast<uint2*>(g_xh + i) = ph;
    *reinterpret_cast<uint2*>(g_xl + i) = pl;
}

// ============ main kernel ============
__device__ __forceinline__ void load_chunk_async(char* smem, int stage, int c,
                                                 int row_base, int n0, int tid){
    char* S = smem + stage * STAGE_BYTES;
    // A: 2048 x 16B (hi+lo), 4 per thread
    #pragma unroll
    for (int it = 0; it < 4; it++){
        int idx = tid + it * TPB;
        int buf = idx >> 10;           // 0 = hi, 1 = lo
        int rem = idx & 1023;
        int row = rem >> 3;
        int j   = rem & 7;             // 16B chunk within 128B row
        const __nv_bfloat16* src = (buf ? g_xl : g_xh)
            + (size_t)(row_base + row) * H_DIM + c * KC + j * 8;
        char* dst = S + (buf ? OFF_AL : OFF_AH) + row * (PITCH_K * 2) + j * 16;
        cp16(dst, src);
    }
    // B: 4096 x 16B (hi+lo), 8 per thread
    #pragma unroll
    for (int it = 0; it < 8; it++){
        int idx = tid + it * TPB;
        int buf = idx >> 11;
        int rem = idx & 2047;
        int row = rem >> 3;            // 0..255
        int j   = rem & 7;
        int grow = (row < 128) ? (n0 + row) : (128 + n0 + row);
        const __nv_bfloat16* src = (buf ? g_Wl : g_Wh)
            + (size_t)grow * H_DIM + c * KC + j * 8;
        char* dst = S + (buf ? OFF_BL : OFF_BH) + row * (PITCH_K * 2) + j * 16;
        cp16(dst, src);
    }
    cp_commit();
}

__global__ void __launch_bounds__(TPB, 1)
fsmn_main_kernel(const float* __restrict__ b_lin,
                 const float* __restrict__ b_mem,
                 float* __restrict__ out){
    extern __shared__ char smem[];
    const int tid  = threadIdx.x;
    const int wid  = tid >> 5;
    const int warp_m = wid >> 2;
    const int warp_n = wid & 3;
    const int row_base = blockIdx.x * TILE_M;
    const int n0 = blockIdx.y * TILE_N;

    wmma::fragment<wmma::accumulator, 16, 16, 16, float> acc1[2][2], acc2[2][2];
    #pragma unroll
    for (int m2 = 0; m2 < 2; m2++)
        #pragma unroll
        for (int n2 = 0; n2 < 2; n2++){
            wmma::fill_fragment(acc1[m2][n2], 0.0f);
            wmma::fill_fragment(acc2[m2][n2], 0.0f);
        }

    const int mrow = warp_m * 32;
    const int ncol = warp_n * 32;

    // prologue: stage 0 <- chunk 0
    load_chunk_async(smem, 0, 0, row_base, n0, tid);

    #pragma unroll
    for (int c = 0; c < NCHUNKS; c++){
        if (c + 1 < NCHUNKS){
            load_chunk_async(smem, (c + 1) & 1, c + 1, row_base, n0, tid);
            cp_wait<1>();
        } else {
            cp_wait<0>();
        }
        __syncthreads();

        char* S = smem + (c & 1) * STAGE_BYTES;
        __nv_bfloat16* Ah = reinterpret_cast<__nv_bfloat16*>(S + OFF_AH);
        __nv_bfloat16* Al = reinterpret_cast<__nv_bfloat16*>(S + OFF_AL);
        __nv_bfloat16* Bh = reinterpret_cast<__nv_bfloat16*>(S + OFF_BH);
        __nv_bfloat16* Bl = reinterpret_cast<__nv_bfloat16*>(S + OFF_BL);

        #pragma unroll
        for (int p = 0; p < 3; p++){
            const __nv_bfloat16* Ab = (p == 2) ? Al : Ah;
            const __nv_bfloat16* Bb = (p == 1) ? Bl : Bh;
            #pragma unroll
            for (int kk = 0; kk < 4; kk++){
                wmma::fragment<wmma::matrix_b, 16, 16, 16, __nv_bfloat16, wmma::col_major> b1[2], b2[2];
                #pragma unroll
                for (int n2 = 0; n2 < 2; n2++){
                    wmma::load_matrix_sync(b1[n2], Bb + (ncol + n2 * 16) * PITCH_K + kk * 16, PITCH_K);
                    wmma::load_matrix_sync(b2[n2], Bb + (128 + ncol + n2 * 16) * PITCH_K + kk * 16, PITCH_K);
                }
                #pragma unroll
                for (int m2 = 0; m2 < 2; m2++){
                    wmma::fragment<wmma::matrix_a, 16, 16, 16, __nv_bfloat16, wmma::row_major> a;
                    wmma::load_matrix_sync(a, Ab + (mrow + m2 * 16) * PITCH_K + kk * 16, PITCH_K);
                    #pragma unroll
                    for (int n2 = 0; n2 < 2; n2++){
                        wmma::mma_sync(acc1[m2][n2], a, b1[n2], acc1[m2][n2]);
                        wmma::mma_sync(acc2[m2][n2], a, b2[n2], acc2[m2][n2]);
                    }
                }
            }
        }
        if (c + 1 < NCHUNKS) __syncthreads();   // compute done before next-next overwrite
    }

    // ================= epilogue =================
    float* S1 = reinterpret_cast<float*>(smem + OFF_S1);
    float* S2 = reinterpret_cast<float*>(smem + OFF_S2);
    const int first_tile = ((blockIdx.x & (TILES_PER_BATCH - 1)) == 0);
    const int col = tid & 63;
    const int rg  = tid >> 6;

    #pragma unroll
    for (int h = 0; h < 2; h++){
        __syncthreads();
        if ((warp_n >> 1) == h){
            int cbase = (warp_n & 1) * 32;
            #pragma unroll
            for (int m2 = 0; m2 < 2; m2++)
                #pragma unroll
                for (int n2 = 0; n2 < 2; n2++){
                    wmma::store_matrix_sync(S1 + (mrow + m2 * 16) * PITCH_E + cbase + n2 * 16,
                                            acc1[m2][n2], PITCH_E, wmma::mem_row_major);
                    wmma::store_matrix_sync(S2 + (mrow + m2 * 16) * PITCH_E + cbase + n2 * 16,
                                            acc2[m2][n2], PITCH_E, wmma::mem_row_major);
                }
        }
        __syncthreads();

        int gcol = n0 + h * 64 + col;
        float bsum = b_lin[gcol] + b_mem[gcol];
        int r0 = rg * 16;
        float sum8 = 0.f;
        #pragma unroll
        for (int d = 1; d <= 8; d++){
            int rr = r0 - d;
            if (rr >= 0) sum8 += S2[rr * PITCH_E + col];
        }
        #pragma unroll
        for (int i = 0; i < 16; i++){
            int r = r0 + i;
            float cur  = S2[r * PITCH_E + col];
            float wsum = sum8 + cur;
            float inv  = (first_tile && r < 8) ? (1.f / (float)(r + 1)) : (1.f / 9.f);
            out[(size_t)(row_base + r) * H_DIM + gcol] = S1[r * PITCH_E + col] + bsum + wsum * inv;
            if (r >= 120)
                g_edge[((size_t)blockIdx.x * 8 + (r - 120)) * H_DIM + gcol] = cur;
            float drop = (r >= 8) ? S2[(r - 8) * PITCH_E + col] : 0.f;
            sum8 += cur - drop;
        }
    }
}

// ============ kernel 2: patch cross-tile window contributions ============
__global__ void fsmn_fix_kernel(float* __restrict__ out){
    int bid = blockIdx.x;
    int b  = bid / (TILES_PER_BATCH - 1);
    int jt = bid % (TILES_PER_BATCH - 1) + 1;
    int prev_tile = b * TILES_PER_BATCH + jt - 1;
    int n = threadIdx.x;
    const float* e = &g_edge[(size_t)prev_tile * 8 * H_DIM];
    size_t obase = (size_t)(b * TILES_PER_BATCH + jt) * TILE_M * H_DIM;
    float suf = 0.f;
    #pragma unroll
    for (int jr = 7; jr >= 0; jr--){
        suf += e[jr * H_DIM + n];
        out[obase + (size_t)jr * H_DIM + n] += suf * (1.f / 9.f);
    }
}

// ============ launch ============
extern "C" void kernel_launch(void* const* d_in, const int* in_sizes, int n_in,
                              void* d_out, int out_size){
    const float* x     = (const float*)d_in[0];
    const float* W_lin = (const float*)d_in[1];
    const float* b_lin = (const float*)d_in[2];
    const float* W_mem = (const float*)d_in[3];
    const float* b_mem = (const float*)d_in[4];
    float* out = (float*)d_out;

    cudaFuncSetAttribute(fsmn_main_kernel, cudaFuncAttributeMaxDynamicSharedMemorySize, SMEM_TOTAL);

    fsmn_convw_kernel<<<N_TOT, H_DIM>>>(W_lin, W_mem);
    fsmn_convx_kernel<<<(int)(((size_t)NROWS_TOTAL * H_DIM) / (512 * 4)), 512>>>(x);
    fsmn_main_kernel<<<dim3(N_TILES, 2), TPB, SMEM_TOTAL>>>(b_lin, b_mem, out);
    fsmn_fix_kernel<<<B_DIM * (TILES_PER_BATCH - 1), H_DIM>>>(out);
}

// round 4
// speedup vs baseline: 3.0749x; 2.9772x over previous
#include <cuda_runtime.h>
#include <cuda_fp16.h>
#include <mma.h>
#include <cstdint>

using namespace nvcuda;

// ---------------- Problem constants ----------------
#define B_DIM 16
#define T_DIM 8192
#define H_DIM 256
#define N_TOT 512            // rows of [W_lin; W_mem]
#define TILE_M 128           // rows per CTA
#define TILE_N 128           // output cols per CTA -> grid.y = 2
#define KC 64                // k-chunk
#define NCHUNKS 4
#define N_TILES 1024         // (B*T)/TILE_M
#define TILES_PER_BATCH 64
#define TPB 512
#define NROWS_TOTAL (B_DIM * T_DIM)

// ---------------- SMEM layout (double-buffered, fp16 single precision) ----------------
#define PITCH_K 72                                 // fp16 elems per row (144 B)
#define A_BYTES (TILE_M * PITCH_K * 2)             // 18432
#define B_BYTES (256 * PITCH_K * 2)                // 36864
#define OFF_A 0
#define OFF_B (OFF_A + A_BYTES)
#define STAGE_BYTES (OFF_B + B_BYTES)              // 55296
#define SMEM_TOTAL (2 * STAGE_BYTES)               // 110592
// epilogue staging (fp32, pitch 68) reuses the buffers
#define PITCH_E 68
#define OFF_S1 0
#define OFF_S2 (TILE_M * PITCH_E * 4)              // 34816 ; S1+S2 = 69632 < SMEM_TOTAL

// ---------------- Device scratch ----------------
__device__ __half g_Wf[N_TOT * H_DIM];
__device__ __half g_xf[(size_t)NROWS_TOTAL * H_DIM];
__device__ float g_edge[(size_t)N_TILES * 8 * H_DIM];

__device__ __forceinline__ uint32_t smem_u32(const void* p){
    uint32_t a;
    asm("{ .reg .u64 t; cvta.to.shared.u64 t, %1; cvt.u32.u64 %0, t; }" : "=r"(a) : "l"(p));
    return a;
}
__device__ __forceinline__ void cp16(void* dst, const void* src){
    uint32_t d = smem_u32(dst);
    asm volatile("cp.async.cg.shared.global [%0], [%1], 16;" :: "r"(d), "l"(src) : "memory");
}
__device__ __forceinline__ void cp_commit(){ asm volatile("cp.async.commit_group;" ::: "memory"); }
template<int N> __device__ __forceinline__ void cp_wait(){ asm volatile("cp.async.wait_group %0;" :: "n"(N) : "memory"); }

// ============ kernel 0: weights -> fp16 ============
__global__ void fsmn_convw_kernel(const float* __restrict__ Wlin, const float* __restrict__ Wmem){
    int r = blockIdx.x, k = threadIdx.x;
    float w = (r < 256) ? Wlin[r * H_DIM + k] : Wmem[(r - 256) * H_DIM + k];
    g_Wf[r * H_DIM + k] = __float2half(w);
}

// ============ kernel 0b: x -> fp16 ============
__global__ void __launch_bounds__(512) fsmn_convx_kernel(const float* __restrict__ x){
    size_t i = ((size_t)blockIdx.x * 512 + threadIdx.x) * 8;
    float4 v0 = *reinterpret_cast<const float4*>(x + i);
    float4 v1 = *reinterpret_cast<const float4*>(x + i + 4);
    __half2 h0 = __floats2half2_rn(v0.x, v0.y);
    __half2 h1 = __floats2half2_rn(v0.z, v0.w);
    __half2 h2 = __floats2half2_rn(v1.x, v1.y);
    __half2 h3 = __floats2half2_rn(v1.z, v1.w);
    uint4 p;
    p.x = *reinterpret_cast<uint32_t*>(&h0);
    p.y = *reinterpret_cast<uint32_t*>(&h1);
    p.z = *reinterpret_cast<uint32_t*>(&h2);
    p.w = *reinterpret_cast<uint32_t*>(&h3);
    *reinterpret_cast<uint4*>(g_xf + i) = p;
}

// ============ main kernel ============
__device__ __forceinline__ void load_chunk_async(char* smem, int stage, int c,
                                                 int row_base, int n0, int tid){
    char* S = smem + stage * STAGE_BYTES;
    // A: 128 rows x 64 fp16 = 1024 x 16B, 2 per thread
    #pragma unroll
    for (int it = 0; it < 2; it++){
        int idx = tid + it * TPB;
        int row = idx >> 3;
        int j   = idx & 7;
        const __half* src = g_xf + (size_t)(row_base + row) * H_DIM + c * KC + j * 8;
        cp16(S + OFF_A + row * (PITCH_K * 2) + j * 16, src);
    }
    // B: 256 rows x 64 fp16 = 2048 x 16B, 4 per thread
    #pragma unroll
    for (int it = 0; it < 4; it++){
        int idx = tid + it * TPB;
        int row = idx >> 3;            // 0..255
        int j   = idx & 7;
        int grow = (row < 128) ? (n0 + row) : (128 + n0 + row);  // z1 rows then z2 rows
        const __half* src = g_Wf + (size_t)grow * H_DIM + c * KC + j * 8;
        cp16(S + OFF_B + row * (PITCH_K * 2) + j * 16, src);
    }
    cp_commit();
}

__global__ void __launch_bounds__(TPB, 1)
fsmn_main_kernel(const float* __restrict__ b_lin,
                 const float* __restrict__ b_mem,
                 float* __restrict__ out){
    extern __shared__ char smem[];
    const int tid  = threadIdx.x;
    const int wid  = tid >> 5;
    const int warp_m = wid >> 2;
    const int warp_n = wid & 3;
    const int row_base = blockIdx.x * TILE_M;
    const int n0 = blockIdx.y * TILE_N;

    wmma::fragment<wmma::accumulator, 16, 16, 16, float> acc1[2][2], acc2[2][2];
    #pragma unroll
    for (int m2 = 0; m2 < 2; m2++)
        #pragma unroll
        for (int n2 = 0; n2 < 2; n2++){
            wmma::fill_fragment(acc1[m2][n2], 0.0f);
            wmma::fill_fragment(acc2[m2][n2], 0.0f);
        }

    const int mrow = warp_m * 32;
    const int ncol = warp_n * 32;

    load_chunk_async(smem, 0, 0, row_base, n0, tid);

    #pragma unroll
    for (int c = 0; c < NCHUNKS; c++){
        if (c + 1 < NCHUNKS){
            load_chunk_async(smem, (c + 1) & 1, c + 1, row_base, n0, tid);
            cp_wait<1>();
        } else {
            cp_wait<0>();
        }
        __syncthreads();

        char* S = smem + (c & 1) * STAGE_BYTES;
        __half* A = reinterpret_cast<__half*>(S + OFF_A);
        __half* Bm = reinterpret_cast<__half*>(S + OFF_B);

        #pragma unroll
        for (int kk = 0; kk < 4; kk++){
            wmma::fragment<wmma::matrix_b, 16, 16, 16, __half, wmma::col_major> b1[2], b2[2];
            #pragma unroll
            for (int n2 = 0; n2 < 2; n2++){
                wmma::load_matrix_sync(b1[n2], Bm + (ncol + n2 * 16) * PITCH_K + kk * 16, PITCH_K);
                wmma::load_matrix_sync(b2[n2], Bm + (128 + ncol + n2 * 16) * PITCH_K + kk * 16, PITCH_K);
            }
            #pragma unroll
            for (int m2 = 0; m2 < 2; m2++){
                wmma::fragment<wmma::matrix_a, 16, 16, 16, __half, wmma::row_major> a;
                wmma::load_matrix_sync(a, A + (mrow + m2 * 16) * PITCH_K + kk * 16, PITCH_K);
                #pragma unroll
                for (int n2 = 0; n2 < 2; n2++){
                    wmma::mma_sync(acc1[m2][n2], a, b1[n2], acc1[m2][n2]);
                    wmma::mma_sync(acc2[m2][n2], a, b2[n2], acc2[m2][n2]);
                }
            }
        }
        if (c + 1 < NCHUNKS) __syncthreads();
    }

    // ================= epilogue =================
    float* S1 = reinterpret_cast<float*>(smem + OFF_S1);
    float* S2 = reinterpret_cast<float*>(smem + OFF_S2);
    const int first_tile = ((blockIdx.x & (TILES_PER_BATCH - 1)) == 0);
    const int col = tid & 63;
    const int rg  = tid >> 6;

    #pragma unroll
    for (int h = 0; h < 2; h++){
        __syncthreads();
        if ((warp_n >> 1) == h){
            int cbase = (warp_n & 1) * 32;
            #pragma unroll
            for (int m2 = 0; m2 < 2; m2++)
                #pragma unroll
                for (int n2 = 0; n2 < 2; n2++){
                    wmma::store_matrix_sync(S1 + (mrow + m2 * 16) * PITCH_E + cbase + n2 * 16,
                                            acc1[m2][n2], PITCH_E, wmma::mem_row_major);
                    wmma::store_matrix_sync(S2 + (mrow + m2 * 16) * PITCH_E + cbase + n2 * 16,
                                            acc2[m2][n2], PITCH_E, wmma::mem_row_major);
                }
        }
        __syncthreads();

        int gcol = n0 + h * 64 + col;
        float bsum = b_lin[gcol] + b_mem[gcol];
        int r0 = rg * 16;
        float sum8 = 0.f;
        #pragma unroll
        for (int d = 1; d <= 8; d++){
            int rr = r0 - d;
            if (rr >= 0) sum8 += S2[rr * PITCH_E + col];
        }
        #pragma unroll
        for (int i = 0; i < 16; i++){
            int r = r0 + i;
            float cur  = S2[r * PITCH_E + col];
            float wsum = sum8 + cur;
            float inv  = (first_tile && r < 8) ? (1.f / (float)(r + 1)) : (1.f / 9.f);
            out[(size_t)(row_base + r) * H_DIM + gcol] = S1[r * PITCH_E + col] + bsum + wsum * inv;
            if (r >= 120)
                g_edge[((size_t)blockIdx.x * 8 + (r - 120)) * H_DIM + gcol] = cur;
            float drop = (r >= 8) ? S2[(r - 8) * PITCH_E + col] : 0.f;
            sum8 += cur - drop;
        }
    }
}

// ============ kernel 2: patch cross-tile window contributions ============
__global__ void fsmn_fix_kernel(float* __restrict__ out){
    int bid = blockIdx.x;
    int b  = bid / (TILES_PER_BATCH - 1);
    int jt = bid % (TILES_PER_BATCH - 1) + 1;
    int prev_tile = b * TILES_PER_BATCH + jt - 1;
    int n = threadIdx.x;
    const float* e = &g_edge[(size_t)prev_tile * 8 * H_DIM];
    size_t obase = (size_t)(b * TILES_PER_BATCH + jt) * TILE_M * H_DIM;
    float suf = 0.f;
    #pragma unroll
    for (int jr = 7; jr >= 0; jr--){
        suf += e[jr * H_DIM + n];
        out[obase + (size_t)jr * H_DIM + n] += suf * (1.f / 9.f);
    }
}

// ============ launch ============
extern "C" void kernel_launch(void* const* d_in, const int* in_sizes, int n_in,
                              void* d_out, int out_size){
    const float* x     = (const float*)d_in[0];
    const float* W_lin = (const float*)d_in[1];
    const float* b_lin = (const float*)d_in[2];
    const float* W_mem = (const float*)d_in[3];
    const float* b_mem = (const float*)d_in[4];
    float* out = (float*)d_out;

    cudaFuncSetAttribute(fsmn_main_kernel, cudaFuncAttributeMaxDynamicSharedMemorySize, SMEM_TOTAL);

    fsmn_convw_kernel<<<N_TOT, H_DIM>>>(W_lin, W_mem);
    fsmn_convx_kernel<<<(int)(((size_t)NROWS_TOTAL * H_DIM) / (512 * 8)), 512>>>(x);
    fsmn_main_kernel<<<dim3(N_TILES, 2), TPB, SMEM_TOTAL>>>(b_lin, b_mem, out);
    fsmn_fix_kernel<<<B_DIM * (TILES_PER_BATCH - 1), H_DIM>>>(out);
}

// round 7
// speedup vs baseline: 3.3272x; 1.0821x over previous
#include <cuda_runtime.h>
#include <cuda_fp16.h>
#include <mma.h>
#include <cstdint>

using namespace nvcuda;

// ---------------- Problem constants ----------------
#define B_DIM 16
#define T_DIM 8192
#define H_DIM 256
#define N_TOT 512            // rows of [W_lin; W_mem]
#define TILE_M 128
#define TILE_N 128           // grid.y = 2
#define KC 64
#define NCHUNKS 4
#define N_TILES 1024
#define TILES_PER_BATCH 64
#define TPB 256              // 8 warps, warp tile 64x32 (dual GEMM)
#define NROWS_TOTAL (B_DIM * T_DIM)

// ---------------- SMEM layout: 4 resident chunks ----------------
#define PITCH_K 72                                  // fp16/row (144 B)
#define A_BYTES (TILE_M * PITCH_K * 2)              // 18432
#define B_BYTES (256 * PITCH_K * 2)                 // 36864
#define OFF_A(c) ((c) * A_BYTES)                    // 0..73728
#define OFF_B(c) (NCHUNKS * A_BYTES + (c) * B_BYTES)
#define SMEM_TOTAL (NCHUNKS * (A_BYTES + B_BYTES))  // 221184
// epilogue staging (fp32, pitch 68) reuses buffers
#define PITCH_E 68
#define OFF_S1 0
#define OFF_S2 (TILE_M * PITCH_E * 4)               // 34816

// ---------------- Device scratch ----------------
__device__ __half g_Wf[N_TOT * H_DIM];
__device__ __half g_xf[(size_t)NROWS_TOTAL * H_DIM];
__device__ float g_edge[(size_t)N_TILES * 8 * H_DIM];

__device__ __forceinline__ uint32_t smem_u32(const void* p){
    uint32_t a;
    asm("{ .reg .u64 t; cvta.to.shared.u64 t, %1; cvt.u32.u64 %0, t; }" : "=r"(a) : "l"(p));
    return a;
}
__device__ __forceinline__ void cp16(void* dst, const void* src){
    uint32_t d = smem_u32(dst);
    asm volatile("cp.async.cg.shared.global [%0], [%1], 16;" :: "r"(d), "l"(src) : "memory");
}
__device__ __forceinline__ void cp_commit(){ asm volatile("cp.async.commit_group;" ::: "memory"); }
template<int N> __device__ __forceinline__ void cp_wait(){ asm volatile("cp.async.wait_group %0;" :: "n"(N) : "memory"); }

// ============ kernel 0: weights -> fp16 ============
__global__ void fsmn_convw_kernel(const float* __restrict__ Wlin, const float* __restrict__ Wmem){
    int r = blockIdx.x, k = threadIdx.x;
    float w = (r < 256) ? Wlin[r * H_DIM + k] : Wmem[(r - 256) * H_DIM + k];
    g_Wf[r * H_DIM + k] = __float2half(w);
}

// ============ kernel 0b: x -> fp16 ============
__global__ void __launch_bounds__(512) fsmn_convx_kernel(const float* __restrict__ x){
    size_t i = ((size_t)blockIdx.x * 512 + threadIdx.x) * 8;
    float4 v0 = *reinterpret_cast<const float4*>(x + i);
    float4 v1 = *reinterpret_cast<const float4*>(x + i + 4);
    __half2 h0 = __floats2half2_rn(v0.x, v0.y);
    __half2 h1 = __floats2half2_rn(v0.z, v0.w);
    __half2 h2 = __floats2half2_rn(v1.x, v1.y);
    __half2 h3 = __floats2half2_rn(v1.z, v1.w);
    uint4 p;
    p.x = *reinterpret_cast<uint32_t*>(&h0);
    p.y = *reinterpret_cast<uint32_t*>(&h1);
    p.z = *reinterpret_cast<uint32_t*>(&h2);
    p.w = *reinterpret_cast<uint32_t*>(&h3);
    *reinterpret_cast<uint4*>(g_xf + i) = p;
}

// ============ main kernel ============
__device__ __forceinline__ void load_chunk_async(char* smem, int c,
                                                 int row_base, int n0, int tid){
    // A: 128 rows x 64 fp16 = 1024 x 16B, 4/thread
    #pragma unroll
    for (int it = 0; it < 4; it++){
        int idx = tid + it * TPB;
        int row = idx >> 3;
        int j   = idx & 7;
        const __half* src = g_xf + (size_t)(row_base + row) * H_DIM + c * KC + j * 8;
        cp16(smem + OFF_A(c) + row * (PITCH_K * 2) + j * 16, src);
    }
    // B: 256 rows x 64 fp16 = 2048 x 16B, 8/thread
    #pragma unroll
    for (int it = 0; it < 8; it++){
        int idx = tid + it * TPB;
        int row = idx >> 3;
        int j   = idx & 7;
        int grow = (row < 128) ? (n0 + row) : (128 + n0 + row);
        const __half* src = g_Wf + (size_t)grow * H_DIM + c * KC + j * 8;
        cp16(smem + OFF_B(c) + row * (PITCH_K * 2) + j * 16, src);
    }
    cp_commit();
}

__global__ void __launch_bounds__(TPB, 1)
fsmn_main_kernel(const float* __restrict__ b_lin,
                 const float* __restrict__ b_mem,
                 float* __restrict__ out){
    extern __shared__ char smem[];
    const int tid  = threadIdx.x;
    const int wid  = tid >> 5;
    const int warp_m = wid >> 2;          // 0..1 -> rows warp_m*64
    const int warp_n = wid & 3;           // 0..3 -> cols warp_n*32
    const int row_base = blockIdx.x * TILE_M;
    const int n0 = blockIdx.y * TILE_N;

    wmma::fragment<wmma::accumulator, 16, 16, 16, float> acc1[4][2], acc2[4][2];
    #pragma unroll
    for (int m4 = 0; m4 < 4; m4++)
        #pragma unroll
        for (int n2 = 0; n2 < 2; n2++){
            wmma::fill_fragment(acc1[m4][n2], 0.0f);
            wmma::fill_fragment(acc2[m4][n2], 0.0f);
        }

    const int mrow = warp_m * 64;
    const int ncol = warp_n * 32;

    // prologue: issue ALL chunk loads (4 commit groups)
    #pragma unroll
    for (int c = 0; c < NCHUNKS; c++)
        load_chunk_async(smem, c, row_base, n0, tid);

    #pragma unroll
    for (int c = 0; c < NCHUNKS; c++){
        if (c == 0) cp_wait<3>();
        else if (c == 1) cp_wait<2>();
        else if (c == 2) cp_wait<1>();
        else cp_wait<0>();
        __syncthreads();

        __half* A  = reinterpret_cast<__half*>(smem + OFF_A(c));
        __half* Bm = reinterpret_cast<__half*>(smem + OFF_B(c));

        #pragma unroll
        for (int kk = 0; kk < 4; kk++){
            wmma::fragment<wmma::matrix_b, 16, 16, 16, __half, wmma::col_major> b1[2], b2[2];
            #pragma unroll
            for (int n2 = 0; n2 < 2; n2++){
                wmma::load_matrix_sync(b1[n2], Bm + (ncol + n2 * 16) * PITCH_K + kk * 16, PITCH_K);
                wmma::load_matrix_sync(b2[n2], Bm + (128 + ncol + n2 * 16) * PITCH_K + kk * 16, PITCH_K);
            }
            #pragma unroll
            for (int m4 = 0; m4 < 4; m4++){
                wmma::fragment<wmma::matrix_a, 16, 16, 16, __half, wmma::row_major> a;
                wmma::load_matrix_sync(a, A + (mrow + m4 * 16) * PITCH_K + kk * 16, PITCH_K);
                #pragma unroll
                for (int n2 = 0; n2 < 2; n2++){
                    wmma::mma_sync(acc1[m4][n2], a, b1[n2], acc1[m4][n2]);
                    wmma::mma_sync(acc2[m4][n2], a, b2[n2], acc2[m4][n2]);
                }
            }
        }
    }

    // ================= epilogue =================
    float* S1 = reinterpret_cast<float*>(smem + OFF_S1);
    float* S2 = reinterpret_cast<float*>(smem + OFF_S2);
    const int first_tile = ((blockIdx.x & (TILES_PER_BATCH - 1)) == 0);
    const int col = tid & 63;
    const int rg  = tid >> 6;            // 0..3 -> rows rg*32..+31

    #pragma unroll
    for (int h = 0; h < 2; h++){
        __syncthreads();
        if ((warp_n >> 1) == h){
            int cbase = (warp_n & 1) * 32;
            #pragma unroll
            for (int m4 = 0; m4 < 4; m4++)
                #pragma unroll
                for (int n2 = 0; n2 < 2; n2++){
                    wmma::store_matrix_sync(S1 + (mrow + m4 * 16) * PITCH_E + cbase + n2 * 16,
                                            acc1[m4][n2], PITCH_E, wmma::mem_row_major);
                    wmma::store_matrix_sync(S2 + (mrow + m4 * 16) * PITCH_E + cbase + n2 * 16,
                                            acc2[m4][n2], PITCH_E, wmma::mem_row_major);
                }
        }
        __syncthreads();

        int gcol = n0 + h * 64 + col;
        float bsum = b_lin[gcol] + b_mem[gcol];
        int r0 = rg * 32;
        float sum8 = 0.f;
        #pragma unroll
        for (int d = 1; d <= 8; d++){
            int rr = r0 - d;
            if (rr >= 0) sum8 += S2[rr * PITCH_E + col];
        }
        #pragma unroll
        for (int i = 0; i < 32; i++){
            int r = r0 + i;
            float cur  = S2[r * PITCH_E + col];
            float wsum = sum8 + cur;
            float inv  = (first_tile && r < 8) ? (1.f / (float)(r + 1)) : (1.f / 9.f);
            out[(size_t)(row_base + r) * H_DIM + gcol] = S1[r * PITCH_E + col] + bsum + wsum * inv;
            if (r >= 120)
                g_edge[((size_t)blockIdx.x * 8 + (r - 120)) * H_DIM + gcol] = cur;
            float drop = (r >= 8) ? S2[(r - 8) * PITCH_E + col] : 0.f;
            sum8 += cur - drop;
        }
    }
}

// ============ kernel 2: patch cross-tile window contributions ============
__global__ void fsmn_fix_kernel(float* __restrict__ out){
    int bid = blockIdx.x;
    int b  = bid / (TILES_PER_BATCH - 1);
    int jt = bid % (TILES_PER_BATCH - 1) + 1;
    int prev_tile = b * TILES_PER_BATCH + jt - 1;
    int n = threadIdx.x;
    const float* e = &g_edge[(size_t)prev_tile * 8 * H_DIM];
    size_t obase = (size_t)(b * TILES_PER_BATCH + jt) * TILE_M * H_DIM;
    float suf = 0.f;
    #pragma unroll
    for (int jr = 7; jr >= 0; jr--){
        suf += e[jr * H_DIM + n];
        out[obase + (size_t)jr * H_DIM + n] += suf * (1.f / 9.f);
    }
}

// ============ launch ============
extern "C" void kernel_launch(void* const* d_in, const int* in_sizes, int n_in,
                              void* d_out, int out_size){
    const float* x     = (const float*)d_in[0];
    const float* W_lin = (const float*)d_in[1];
    const float* b_lin = (const float*)d_in[2];
    const float* W_mem = (const float*)d_in[3];
    const float* b_mem = (const float*)d_in[4];
    float* out = (float*)d_out;

    cudaFuncSetAttribute(fsmn_main_kernel, cudaFuncAttributeMaxDynamicSharedMemorySize, SMEM_TOTAL);

    fsmn_convw_kernel<<<N_TOT, H_DIM>>>(W_lin, W_mem);
    fsmn_convx_kernel<<<(int)(((size_t)NROWS_TOTAL * H_DIM) / (512 * 8)), 512>>>(x);
    fsmn_main_kernel<<<dim3(N_TILES, 2), TPB, SMEM_TOTAL>>>(b_lin, b_mem, out);
    fsmn_fix_kernel<<<B_DIM * (TILES_PER_BATCH - 1), H_DIM>>>(out);
}